// round 1
// baseline (speedup 1.0000x reference)
#include <cuda_runtime.h>
#include <cuda_bf16.h>

#define NEGV (-1.0e30f)

// Problem constants (fixed by the dataset)
#define B    8
#define CIN  64
#define COUT 64
#define H    64
#define W    64

// Tile config
#define TW   32   // output cols per block
#define TH   8    // output rows per block
#define COB  16   // co per block
#define COT  4    // co per thread
#define XS_W 35   // 34 needed cols padded to odd stride (bank-conflict free)
#define XS_H 10   // TH + 2 halo

__global__ __launch_bounds__(256, 4)
void maxconv2d_kernel(const float* __restrict__ x,
                      const float* __restrict__ wgt,
                      float* __restrict__ out)
{
    __shared__ float xs[XS_H * XS_W];   // 350 floats
    __shared__ float ws[COB * 9];       // 144 floats

    const int tid = threadIdx.x;
    const int z   = blockIdx.z;
    const int b   = z >> 2;             // COUT/COB = 4 co-blocks
    const int co0 = (z & 3) * COB;
    const int h0  = blockIdx.y * TH;
    const int w0  = blockIdx.x * TW;

    const int cog = tid >> 6;           // 0..3 : which co-group (of COT)
    const int sp  = tid & 63;           // spatial thread
    const int r   = sp >> 3;            // 0..7 : output row within tile
    const int cg  = (sp & 7) << 2;      // 0,4,...,28 : output col base

    float acc[COT][4];
#pragma unroll
    for (int u = 0; u < COT; ++u)
#pragma unroll
        for (int p = 0; p < 4; ++p)
            acc[u][p] = NEGV;

    const float* xb = x + (size_t)b * CIN * H * W;

    for (int cin = 0; cin < CIN; ++cin) {
        // ---- stage x halo tile (10 x 34 valid, stride 35) ----
        const float* xc = xb + cin * (H * W);
        for (int i = tid; i < XS_H * XS_W; i += 256) {
            int rr = i / XS_W;
            int cc = i - rr * XS_W;
            float v = NEGV;
            int gh = h0 - 1 + rr;
            int gw = w0 - 1 + cc;
            if (cc < TW + 2 && (unsigned)gh < (unsigned)H && (unsigned)gw < (unsigned)W)
                v = xc[gh * W + gw];
            xs[i] = v;
        }
        // ---- stage weights for this cin: COB co x 9 taps ----
        if (tid < COB * 9) {
            int col = tid / 9;
            int tap = tid - col * 9;
            ws[tid] = wgt[((co0 + col) * CIN + cin) * 9 + tap];
        }
        __syncthreads();

        // ---- per-thread x neighborhood: 3 rows x 6 cols ----
        float xv[18];
#pragma unroll
        for (int dr = 0; dr < 3; ++dr)
#pragma unroll
            for (int dc = 0; dc < 6; ++dc)
                xv[dr * 6 + dc] = xs[(r + dr) * XS_W + cg + dc];

#pragma unroll
        for (int u = 0; u < COT; ++u) {
            const float* wp = &ws[(cog * COT + u) * 9];
#pragma unroll
            for (int dr = 0; dr < 3; ++dr) {
#pragma unroll
                for (int dc = 0; dc < 3; ++dc) {
                    const float wv = wp[dr * 3 + dc];   // uniform -> smem broadcast
#pragma unroll
                    for (int p = 0; p < 4; ++p)
                        acc[u][p] = fmaxf(acc[u][p], xv[dr * 6 + dc + p] + wv);
                }
            }
        }
        __syncthreads();
    }

    // ---- epilogue: vectorized stores (16B aligned: cg multiple of 4) ----
#pragma unroll
    for (int u = 0; u < COT; ++u) {
        const int co = co0 + cog * COT + u;
        float* op = out + (((size_t)b * COUT + co) * H + (h0 + r)) * W + w0 + cg;
        float4 v = make_float4(acc[u][0], acc[u][1], acc[u][2], acc[u][3]);
        *reinterpret_cast<float4*>(op) = v;
    }
}

extern "C" void kernel_launch(void* const* d_in, const int* in_sizes, int n_in,
                              void* d_out, int out_size)
{
    const float* x   = (const float*)d_in[0];
    const float* wgt = (const float*)d_in[1];
    float* out       = (float*)d_out;

    dim3 grid(W / TW, H / TH, B * (COUT / COB));   // (2, 8, 32)
    maxconv2d_kernel<<<grid, 256>>>(x, wgt, out);
}

// round 2
// speedup vs baseline: 1.3603x; 1.3603x over previous
#include <cuda_runtime.h>
#include <cuda_bf16.h>

#define NEGV (-1.0e30f)

// Problem constants
#define B    8
#define CIN  64
#define COUT 64
#define H    64
#define W    64
#define HW   (H*W)

// Tiling
#define TW   32           // output cols per block
#define TH   4            // output rows per block
#define COB  16           // co per block
#define COT  4            // co per thread
#define NC   4            // cin staged per barrier pair
#define XS_H (TH + 2)     // 6
#define XS_W 36           // 34 valid cols padded to 36 (16B-aligned rows)
#define XS_C (XS_H * XS_W)   // 216 words per cin
#define WS_C (COB * 12)      // 192 words per cin (9 taps padded to 12)

#define NXS  (NC * XS_C)  // 864
#define NWSV (NC * COB * 9)  // 576 valid weight words

__global__ __launch_bounds__(128)
void maxconv2d_kernel(const float* __restrict__ x,
                      const float* __restrict__ wgt,
                      float* __restrict__ out)
{
    __shared__ __align__(16) float xs[NC * XS_C];   // 3456 B
    __shared__ __align__(16) float ws[NC * WS_C];   // 3072 B

    const int tid  = threadIdx.x;
    const int b    = blockIdx.z >> 2;
    const int co0  = (blockIdx.z & 3) * COB;
    const int h0   = blockIdx.y * TH;
    const int w0   = blockIdx.x * TW;

    const int cog  = tid >> 5;          // warp id == co-group (4 groups of COT)
    const int lane = tid & 31;
    const int r    = lane >> 3;         // 0..3  (quarter-warp = one row -> conflict-free LDS.128)
    const int cg   = (lane & 7) << 2;   // 0,4,...,28

    float acc[COT][4];
#pragma unroll
    for (int u = 0; u < COT; ++u)
#pragma unroll
        for (int p = 0; p < 4; ++p)
            acc[u][p] = NEGV;

    // ---- precompute x staging slots (7 slots cover 864 words) ----
    int  xgo[7];
    bool xok[7];
#pragma unroll
    for (int k = 0; k < 7; ++k) {
        int i  = tid + 128 * k;
        int c  = i / XS_C;
        int rm = i - c * XS_C;
        int rr = rm / XS_W;
        int cc = rm - rr * XS_W;
        int gh = h0 - 1 + rr;
        int gw = w0 - 1 + cc;
        bool v = (cc < TW + 2) && ((unsigned)gh < (unsigned)H) && ((unsigned)gw < (unsigned)W);
        xok[k] = v;
        xgo[k] = c * HW + gh * W + gw;
    }

    // ---- precompute weight staging slots (5 slots cover 576 valid words) ----
    int wgo[5];
    int wso[5];
#pragma unroll
    for (int k = 0; k < 5; ++k) {
        int i  = tid + 128 * k;
        int c  = i / (COB * 9);
        int rm = i - c * (COB * 9);
        int co = rm / 9;
        int tp = rm - co * 9;
        wso[k] = c * WS_C + co * 12 + tp;
        wgo[k] = co * CIN * 9 + c * 9 + tp;
    }

    const float* xb = x + (size_t)b * CIN * HW;
    const float* wb = wgt + (size_t)co0 * CIN * 9;

    for (int it = 0; it < CIN / NC; ++it) {
        const float* xc = xb + it * NC * HW;
        const float* wc = wb + it * NC * 9;

        __syncthreads();   // previous compute done before overwrite

        // stage x (slots 0..5 full, slot 6 partial: i = 768+tid < 864 iff tid < 96)
#pragma unroll
        for (int k = 0; k < 6; ++k) {
            float v = NEGV;
            if (xok[k]) v = xc[xgo[k]];
            xs[tid + 128 * k] = v;
        }
        if (tid < NXS - 128 * 6) {
            float v = NEGV;
            if (xok[6]) v = xc[xgo[6]];
            xs[tid + 128 * 6] = v;
        }
        // stage weights (slots 0..3 full, slot 4 partial: tid < 64)
#pragma unroll
        for (int k = 0; k < 4; ++k)
            ws[wso[k]] = wc[wgo[k]];
        if (tid < NWSV - 128 * 4)
            ws[wso[4]] = wc[wgo[4]];

        __syncthreads();

#pragma unroll
        for (int c = 0; c < NC; ++c) {
            const float* xp = xs + c * XS_C + r * XS_W + cg;
            float xv[3][6];
#pragma unroll
            for (int dr = 0; dr < 3; ++dr) {
                float4 a  = *reinterpret_cast<const float4*>(xp + dr * XS_W);
                float4 bq = *reinterpret_cast<const float4*>(xp + dr * XS_W + 4);
                xv[dr][0] = a.x;  xv[dr][1] = a.y;  xv[dr][2] = a.z;
                xv[dr][3] = a.w;  xv[dr][4] = bq.x; xv[dr][5] = bq.y;
            }
            const float* wp = ws + c * WS_C + cog * (COT * 12);
#pragma unroll
            for (int u = 0; u < COT; ++u) {
                float4 q0 = *reinterpret_cast<const float4*>(wp + u * 12);
                float4 q1 = *reinterpret_cast<const float4*>(wp + u * 12 + 4);
                float  w8 = wp[u * 12 + 8];
                float wv[9] = { q0.x, q0.y, q0.z, q0.w, q1.x, q1.y, q1.z, q1.w, w8 };
#pragma unroll
                for (int dr = 0; dr < 3; ++dr)
#pragma unroll
                    for (int dc = 0; dc < 3; ++dc) {
                        const float wvv = wv[dr * 3 + dc];
#pragma unroll
                        for (int p = 0; p < 4; ++p)
                            acc[u][p] = fmaxf(acc[u][p], xv[dr][dc + p] + wvv);
                    }
            }
        }
    }

    // ---- epilogue: float4 stores ----
#pragma unroll
    for (int u = 0; u < COT; ++u) {
        const int co = co0 + cog * COT + u;
        float* op = out + (((size_t)b * COUT + co) * H + (h0 + r)) * W + w0 + cg;
        *reinterpret_cast<float4*>(op) =
            make_float4(acc[u][0], acc[u][1], acc[u][2], acc[u][3]);
    }
}

extern "C" void kernel_launch(void* const* d_in, const int* in_sizes, int n_in,
                              void* d_out, int out_size)
{
    const float* x   = (const float*)d_in[0];
    const float* wgt = (const float*)d_in[1];
    float* out       = (float*)d_out;

    dim3 grid(W / TW, H / TH, B * (COUT / COB));   // (2, 16, 32) = 1024 blocks
    maxconv2d_kernel<<<grid, 128>>>(x, wgt, out);
}

// round 3
// speedup vs baseline: 1.4858x; 1.0923x over previous
#include <cuda_runtime.h>
#include <cuda_bf16.h>

#define NEGV (-1.0e30f)

// Problem constants
#define B    8
#define CIN  64
#define COUT 64
#define H    64
#define W    64
#define HW   (H*W)

// Tiling
#define TW   32
#define TH   4
#define COB  16
#define COT  4
#define NC   4
#define XS_H (TH + 2)            // 6
#define XS_W 36                  // 34 valid, padded to 36 (16B rows)
#define XS_C (XS_H * XS_W)       // 216
#define WS_C (COB * 12)          // 192
#define NXS  (NC * XS_C)         // 864
#define NWSV (NC * COB * 9)      // 576
#define NITER (CIN / NC)         // 16

__global__ __launch_bounds__(128, 6)
void maxconv2d_kernel(const float* __restrict__ x,
                      const float* __restrict__ wgt,
                      float* __restrict__ out)
{
    __shared__ __align__(16) float xs[2][NXS];        // 2 x 3456 B
    __shared__ __align__(16) float ws[2][NC * WS_C];  // 2 x 3072 B

    const int tid  = threadIdx.x;
    const int b    = blockIdx.z >> 2;
    const int co0  = (blockIdx.z & 3) * COB;
    const int h0   = blockIdx.y * TH;
    const int w0   = blockIdx.x * TW;

    const int cog  = tid >> 5;
    const int lane = tid & 31;
    const int r    = lane >> 3;
    const int cg   = (lane & 7) << 2;

    float acc[COT][4];
#pragma unroll
    for (int u = 0; u < COT; ++u)
#pragma unroll
        for (int p = 0; p < 4; ++p)
            acc[u][p] = NEGV;

    // ---- precompute x staging slots (7 slots cover 864 words) ----
    int  xgo[7];
    bool xok[7];
#pragma unroll
    for (int k = 0; k < 7; ++k) {
        int i  = tid + 128 * k;
        int c  = i / XS_C;
        int rm = i - c * XS_C;
        int rr = rm / XS_W;
        int cc = rm - rr * XS_W;
        int gh = h0 - 1 + rr;
        int gw = w0 - 1 + cc;
        bool v = (i < NXS) && (cc < TW + 2) &&
                 ((unsigned)gh < (unsigned)H) && ((unsigned)gw < (unsigned)W);
        xok[k] = v;
        xgo[k] = v ? (c * HW + gh * W + gw) : 0;
    }

    // ---- precompute weight staging slots (5 slots cover 576 words) ----
    int  wgo[5];
    int  wso[5];
    bool wok[5];
#pragma unroll
    for (int k = 0; k < 5; ++k) {
        int i  = tid + 128 * k;
        int c  = i / (COB * 9);
        int rm = i - c * (COB * 9);
        int co = rm / 9;
        int tp = rm - co * 9;
        wok[k] = (i < NWSV);
        wso[k] = wok[k] ? (c * WS_C + co * 12 + tp) : 0;
        wgo[k] = wok[k] ? (co * CIN * 9 + c * 9 + tp) : 0;
    }

    const float* xb = x   + (size_t)b * CIN * HW;
    const float* wb = wgt + (size_t)co0 * CIN * 9;

    float px[7], pw[5];

    // ---- prologue: prefetch + stage iteration 0 into buffer 0 ----
    {
        const float* xc = xb;
        const float* wc = wb;
#pragma unroll
        for (int k = 0; k < 7; ++k) px[k] = xok[k] ? xc[xgo[k]] : NEGV;
#pragma unroll
        for (int k = 0; k < 5; ++k) pw[k] = wok[k] ? wc[wgo[k]] : 0.0f;
#pragma unroll
        for (int k = 0; k < 7; ++k)
            if (k < 6 || tid < NXS - 768) xs[0][tid + 128 * k] = px[k];
#pragma unroll
        for (int k = 0; k < 5; ++k)
            if (wok[k]) ws[0][wso[k]] = pw[k];
    }
    __syncthreads();

    int buf = 0;
    for (int it = 0; it < NITER; ++it) {
        // ---- prefetch next iteration's data into registers (latency hidden) ----
        const bool more = (it + 1 < NITER);
        if (more) {
            const float* xc = xb + (it + 1) * NC * HW;
            const float* wc = wb + (it + 1) * NC * 9;
#pragma unroll
            for (int k = 0; k < 7; ++k) px[k] = xok[k] ? xc[xgo[k]] : NEGV;
#pragma unroll
            for (int k = 0; k < 5; ++k) pw[k] = wok[k] ? wc[wgo[k]] : 0.0f;
        }

        // ---- compute on current buffer ----
        const float* xsb = xs[buf];
        const float* wsb = ws[buf];
#pragma unroll
        for (int c = 0; c < NC; ++c) {
            const float* xp = xsb + c * XS_C + r * XS_W + cg;
            float xv[3][6];
#pragma unroll
            for (int dr = 0; dr < 3; ++dr) {
                float4 a  = *reinterpret_cast<const float4*>(xp + dr * XS_W);
                float4 bq = *reinterpret_cast<const float4*>(xp + dr * XS_W + 4);
                xv[dr][0] = a.x;  xv[dr][1] = a.y;  xv[dr][2] = a.z;
                xv[dr][3] = a.w;  xv[dr][4] = bq.x; xv[dr][5] = bq.y;
            }
            const float* wp = wsb + c * WS_C + cog * (COT * 12);
#pragma unroll
            for (int u = 0; u < COT; ++u) {
                float4 q0 = *reinterpret_cast<const float4*>(wp + u * 12);
                float4 q1 = *reinterpret_cast<const float4*>(wp + u * 12 + 4);
                float  w8 = wp[u * 12 + 8];
                float wv[9] = { q0.x, q0.y, q0.z, q0.w, q1.x, q1.y, q1.z, q1.w, w8 };
#pragma unroll
                for (int dr = 0; dr < 3; ++dr)
#pragma unroll
                    for (int dc = 0; dc < 3; ++dc) {
                        const float wvv = wv[dr * 3 + dc];
#pragma unroll
                        for (int p = 0; p < 4; ++p)
                            acc[u][p] = fmaxf(acc[u][p], xv[dr][dc + p] + wvv);
                    }
            }
        }

        // ---- store prefetched data into the inactive buffer ----
        if (more) {
            float* xsn = xs[buf ^ 1];
            float* wsn = ws[buf ^ 1];
#pragma unroll
            for (int k = 0; k < 7; ++k)
                if (k < 6 || tid < NXS - 768) xsn[tid + 128 * k] = px[k];
#pragma unroll
            for (int k = 0; k < 5; ++k)
                if (wok[k]) wsn[wso[k]] = pw[k];
        }
        __syncthreads();
        buf ^= 1;
    }

    // ---- epilogue: float4 stores ----
#pragma unroll
    for (int u = 0; u < COT; ++u) {
        const int co = co0 + cog * COT + u;
        float* op = out + (((size_t)b * COUT + co) * H + (h0 + r)) * W + w0 + cg;
        *reinterpret_cast<float4*>(op) =
            make_float4(acc[u][0], acc[u][1], acc[u][2], acc[u][3]);
    }
}

extern "C" void kernel_launch(void* const* d_in, const int* in_sizes, int n_in,
                              void* d_out, int out_size)
{
    const float* x   = (const float*)d_in[0];
    const float* wgt = (const float*)d_in[1];
    float* out       = (float*)d_out;

    dim3 grid(W / TW, H / TH, B * (COUT / COB));   // (2, 16, 32) = 1024 blocks
    maxconv2d_kernel<<<grid, 128>>>(x, wgt, out);
}

// round 4
// speedup vs baseline: 1.5122x; 1.0178x over previous
#include <cuda_runtime.h>
#include <cuda_bf16.h>
#include <cstdint>

#define NEGV (-1.0e30f)

// Problem constants
#define B    8
#define CIN  64
#define COUT 64
#define H    64
#define W    64
#define HW   (H*W)

// Tiling
#define TW   32
#define TH   4
#define COB  16
#define COT  4
#define NC   4
#define XS_H (TH + 2)            // 6
#define XS_W 36                  // 34 valid, padded to 36 (16B rows)
#define XS_C (XS_H * XS_W)       // 216
#define WS_C (COB * 12)          // 192
#define NXS  (NC * XS_C)         // 864
#define NWS  (NC * WS_C)         // 768
#define NWSV (NC * COB * 9)      // 576
#define NITER (CIN / NC)         // 16

#define CP_ASYNC4(dst, src) \
    asm volatile("cp.async.ca.shared.global [%0], [%1], 4;\n" :: "r"(dst), "l"(src))
#define CP_COMMIT() asm volatile("cp.async.commit_group;\n" ::: "memory")
#define CP_WAIT0()  asm volatile("cp.async.wait_group 0;\n" ::: "memory")

__global__ __launch_bounds__(128, 7)
void maxconv2d_kernel(const float* __restrict__ x,
                      const float* __restrict__ wgt,
                      float* __restrict__ out)
{
    __shared__ __align__(16) float xs[2][NXS];   // 2 x 3456 B
    __shared__ __align__(16) float ws[2][NWS];   // 2 x 3072 B

    const int tid  = threadIdx.x;
    const int b    = blockIdx.z >> 2;
    const int co0  = (blockIdx.z & 3) * COB;
    const int h0   = blockIdx.y * TH;
    const int w0   = blockIdx.x * TW;

    const int cog  = tid >> 5;
    const int lane = tid & 31;
    const int r    = lane >> 3;
    const int cg   = (lane & 7) << 2;

    float acc[COT][4];
#pragma unroll
    for (int u = 0; u < COT; ++u)
#pragma unroll
        for (int p = 0; p < 4; ++p)
            acc[u][p] = NEGV;

    // ---- precompute x staging slots (7 slots cover 864 words) ----
    int  xgo[7];
    bool xok[7];
#pragma unroll
    for (int k = 0; k < 7; ++k) {
        int i  = tid + 128 * k;
        int c  = i / XS_C;
        int rm = i - c * XS_C;
        int rr = rm / XS_W;
        int cc = rm - rr * XS_W;
        int gh = h0 - 1 + rr;
        int gw = w0 - 1 + cc;
        bool v = (i < NXS) && (cc < TW + 2) &&
                 ((unsigned)gh < (unsigned)H) && ((unsigned)gw < (unsigned)W);
        xok[k] = v;
        xgo[k] = v ? (c * HW + gh * W + gw) : 0;
    }

    // ---- precompute weight staging slots (5 slots cover 576 valid words) ----
    int  wgo[5];
    int  wso[5];
    bool wok[5];
#pragma unroll
    for (int k = 0; k < 5; ++k) {
        int i  = tid + 128 * k;
        int c  = i / (COB * 9);
        int rm = i - c * (COB * 9);
        int co = rm / 9;
        int tp = rm - co * 9;
        wok[k] = (i < NWSV);
        wso[k] = wok[k] ? (c * WS_C + co * 12 + tp) : 0;
        wgo[k] = wok[k] ? (co * CIN * 9 + c * 9 + tp) : 0;
    }

    const float* xb = x   + (size_t)b * CIN * HW;
    const float* wb = wgt + (size_t)co0 * CIN * 9;

    const uint32_t xs_s = (uint32_t)__cvta_generic_to_shared(&xs[0][0]);
    const uint32_t ws_s = (uint32_t)__cvta_generic_to_shared(&ws[0][0]);

    // ---- prologue: NEG-fill both x buffers (OOB slots persist forever) ----
    {
        float* xf = &xs[0][0];
        for (int i = tid; i < 2 * NXS; i += 128) xf[i] = NEGV;
    }
    __syncthreads();

    // ---- issue stage 0 into buffer 0 ----
    {
        const float* xc = xb;
        const float* wc = wb;
#pragma unroll
        for (int k = 0; k < 7; ++k)
            if (xok[k]) CP_ASYNC4(xs_s + (uint32_t)(tid + 128 * k) * 4u, xc + xgo[k]);
#pragma unroll
        for (int k = 0; k < 5; ++k)
            if (wok[k]) CP_ASYNC4(ws_s + (uint32_t)wso[k] * 4u, wc + wgo[k]);
        CP_COMMIT();
    }

    int buf = 0;
    for (int it = 0; it < NITER; ++it) {
        CP_WAIT0();          // this thread's stage `it` landed
        __syncthreads();     // all threads' arrivals visible; prior compute done

        // ---- issue stage it+1 into inactive buffer (flies under compute) ----
        if (it + 1 < NITER) {
            const float* xc = xb + (it + 1) * NC * HW;
            const float* wc = wb + (it + 1) * NC * 9;
            const uint32_t xd = xs_s + (uint32_t)((buf ^ 1) * NXS) * 4u;
            const uint32_t wd = ws_s + (uint32_t)((buf ^ 1) * NWS) * 4u;
#pragma unroll
            for (int k = 0; k < 7; ++k)
                if (xok[k]) CP_ASYNC4(xd + (uint32_t)(tid + 128 * k) * 4u, xc + xgo[k]);
#pragma unroll
            for (int k = 0; k < 5; ++k)
                if (wok[k]) CP_ASYNC4(wd + (uint32_t)wso[k] * 4u, wc + wgo[k]);
            CP_COMMIT();
        }

        // ---- compute on current buffer ----
        const float* xsb = xs[buf];
        const float* wsb = ws[buf];
#pragma unroll
        for (int c = 0; c < NC; ++c) {
            const float* xp = xsb + c * XS_C + r * XS_W + cg;
            float xv[3][6];
#pragma unroll
            for (int dr = 0; dr < 3; ++dr) {
                float4 a  = *reinterpret_cast<const float4*>(xp + dr * XS_W);
                float4 bq = *reinterpret_cast<const float4*>(xp + dr * XS_W + 4);
                xv[dr][0] = a.x;  xv[dr][1] = a.y;  xv[dr][2] = a.z;
                xv[dr][3] = a.w;  xv[dr][4] = bq.x; xv[dr][5] = bq.y;
            }
            const float* wp = wsb + c * WS_C + cog * (COT * 12);
#pragma unroll
            for (int u = 0; u < COT; ++u) {
                float4 q0 = *reinterpret_cast<const float4*>(wp + u * 12);
                float4 q1 = *reinterpret_cast<const float4*>(wp + u * 12 + 4);
                float  w8 = wp[u * 12 + 8];
                float wv[9] = { q0.x, q0.y, q0.z, q0.w, q1.x, q1.y, q1.z, q1.w, w8 };
#pragma unroll
                for (int dr = 0; dr < 3; ++dr)
#pragma unroll
                    for (int dc = 0; dc < 3; ++dc) {
                        const float wvv = wv[dr * 3 + dc];
#pragma unroll
                        for (int p = 0; p < 4; ++p)
                            acc[u][p] = fmaxf(acc[u][p], xv[dr][dc + p] + wvv);
                    }
            }
        }
        buf ^= 1;
    }

    // ---- epilogue: float4 stores ----
#pragma unroll
    for (int u = 0; u < COT; ++u) {
        const int co = co0 + cog * COT + u;
        float* op = out + (((size_t)b * COUT + co) * H + (h0 + r)) * W + w0 + cg;
        *reinterpret_cast<float4*>(op) =
            make_float4(acc[u][0], acc[u][1], acc[u][2], acc[u][3]);
    }
}

extern "C" void kernel_launch(void* const* d_in, const int* in_sizes, int n_in,
                              void* d_out, int out_size)
{
    const float* x   = (const float*)d_in[0];
    const float* wgt = (const float*)d_in[1];
    float* out       = (float*)d_out;

    dim3 grid(W / TW, H / TH, B * (COUT / COB));   // 1024 blocks
    maxconv2d_kernel<<<grid, 128>>>(x, wgt, out);
}

// round 6
// speedup vs baseline: 2.2629x; 1.4964x over previous
#include <cuda_runtime.h>
#include <cuda_fp16.h>
#include <cstdint>

#define NEGF (-1.0e30f)
#define NEGH (-60000.0f)

// Problem constants
#define B    8
#define CIN  64
#define COUT 64
#define H    64
#define W    64
#define HW   (H*W)

// Padded x (fp16): [B][CIN][66][72] halves (halo + width pad for alignment)
#define XPH  66
#define XPW  72           // halves per row
#define XPWW (XPW/2)      // 36 uint32 words per row
#define XPC  (XPH*XPWW)   // 2376 words per cin-plane

// Dup weights (half2): [CIN][COUT][12]
#define WPC  12

// Tiling
#define TW   32
#define TH   4
#define COB  16
#define COT  4
#define NC   4
#define XROW 18                    // uint32 words per staged row (36 halves)
#define XS_C (6*XROW)              // 108 words per cin
#define NXSW (NC*XS_C)             // 432 words per stage
#define WS_C (COB*WPC)             // 192 words per cin
#define NWSW (NC*WS_C)             // 768 words per stage
#define NITER (CIN/NC)             // 16

__device__ __half2 xpad_g[(size_t)B*CIN*XPC];      // as half2 words
__device__ __half2 wdup_g[CIN*COUT*WPC];

#define CP_ASYNC4(dst, src) \
    asm volatile("cp.async.ca.shared.global [%0], [%1], 4;\n" :: "r"(dst), "l"(src))
#define CP_COMMIT() asm volatile("cp.async.commit_group;\n" ::: "memory")
#define CP_WAIT0()  asm volatile("cp.async.wait_group 0;\n" ::: "memory")

// ---- prep 1: pad + convert x to fp16 ----
__global__ void prep_x(const float* __restrict__ x)
{
    int idx = blockIdx.x * blockDim.x + threadIdx.x;          // one half2 word
    const int total = B * CIN * XPC;
    if (idx >= total) return;
    int ww2 = idx % XPWW;
    int t   = idx / XPWW;
    int hh  = t % XPH;
    int bc  = t / XPH;           // b*CIN + c
    float v0 = NEGH, v1 = NEGH;
    int w0 = ww2 * 2,  w1 = w0 + 1;
    if (hh >= 1 && hh <= H) {
        const float* row = x + (size_t)bc * HW + (hh - 1) * W;
        if (w0 >= 1 && w0 <= W) v0 = row[w0 - 1];
        if (w1 >= 1 && w1 <= W) v1 = row[w1 - 1];
    }
    xpad_g[idx] = __floats2half2_rn(v0, v1);
}

// ---- prep 2: duplicate-convert weights ----
__global__ void prep_w(const float* __restrict__ wgt)
{
    int idx = blockIdx.x * blockDim.x + threadIdx.x;
    if (idx >= CIN * COUT * WPC) return;
    int t  = idx % WPC;
    int q  = idx / WPC;
    int co = q % COUT;
    int ci = q / COUT;
    float v = (t < 9) ? wgt[(co * CIN + ci) * 9 + t] : 0.0f;
    __half h = __float2half(v);
    wdup_g[idx] = __halves2half2(h, h);
}

__global__ __launch_bounds__(128, 7)
void maxconv2d_kernel(float* __restrict__ out)
{
    __shared__ __align__(16) unsigned xs[2][NXSW];   // half2 words
    __shared__ __align__(16) unsigned ws[2][NWSW];

    const int tid  = threadIdx.x;
    const int b    = blockIdx.z >> 2;
    const int co0  = (blockIdx.z & 3) * COB;
    const int h0   = blockIdx.y * TH;
    const int w0   = blockIdx.x * TW;

    const int cog  = tid >> 5;
    const int lane = tid & 31;
    const int r    = lane >> 3;
    const int cg   = (lane & 7) << 2;   // output col base (pixels)

    const __half2 NEG2 = __float2half2_rn(NEGH);
    __half2 A[COT][2];
#pragma unroll
    for (int u = 0; u < COT; ++u) { A[u][0] = NEG2; A[u][1] = NEG2; }

    // ---- x staging slots: 432 words, 4 slots (last partial tid<48) ----
    int xgo[4];
#pragma unroll
    for (int k = 0; k < 4; ++k) {
        int i  = tid + 128 * k;
        int c  = i / XS_C;
        int rm = i - c * XS_C;
        int rr = rm / XROW;
        int wc = rm - rr * XROW;
        xgo[k] = c * XPC + (h0 + rr) * XPWW + (w0 >> 1) + wc;
    }
    // ---- w staging slots: 768 words, 6 exact slots ----
    int wgo[6], wso[6];
#pragma unroll
    for (int k = 0; k < 6; ++k) {
        int i  = tid + 128 * k;
        int c  = i / WS_C;
        int rm = i - c * WS_C;
        int co = rm / WPC;
        int t  = rm - co * WPC;
        wso[k] = c * WS_C + co * WPC + t;
        wgo[k] = (c * COUT + co0 + co) * WPC + t;     // + it*NC*COUT*WPC
    }

    const __half2* xb = xpad_g + (size_t)b * CIN * XPC;
    const __half2* wb = wdup_g;

    const uint32_t xs_s = (uint32_t)__cvta_generic_to_shared(&xs[0][0]);
    const uint32_t ws_s = (uint32_t)__cvta_generic_to_shared(&ws[0][0]);

    // ---- stage 0 ----
    {
#pragma unroll
        for (int k = 0; k < 4; ++k)
            if (k < 3 || tid < NXSW - 384)
                CP_ASYNC4(xs_s + (uint32_t)(tid + 128 * k) * 4u, xb + xgo[k]);
#pragma unroll
        for (int k = 0; k < 6; ++k)
            CP_ASYNC4(ws_s + (uint32_t)wso[k] * 4u, wb + wgo[k]);
        CP_COMMIT();
    }

    int buf = 0;
    for (int it = 0; it < NITER; ++it) {
        CP_WAIT0();
        __syncthreads();

        if (it + 1 < NITER) {
            const __half2* xc = xb + (size_t)(it + 1) * NC * XPC;
            const __half2* wc = wb + (size_t)(it + 1) * NC * COUT * WPC;
            const uint32_t xd = xs_s + (uint32_t)((buf ^ 1) * NXSW) * 4u;
            const uint32_t wd = ws_s + (uint32_t)((buf ^ 1) * NWSW) * 4u;
#pragma unroll
            for (int k = 0; k < 4; ++k)
                if (k < 3 || tid < NXSW - 384)
                    CP_ASYNC4(xd + (uint32_t)(tid + 128 * k) * 4u, xc + xgo[k]);
#pragma unroll
            for (int k = 0; k < 6; ++k)
                CP_ASYNC4(wd + (uint32_t)wso[k] * 4u, wc + wgo[k]);
            CP_COMMIT();
        }

        // ---- compute ----
        const unsigned* xsb = xs[buf];
        const unsigned* wsb = ws[buf];
#pragma unroll
        for (int c = 0; c < NC; ++c) {
            // windows: xw[dr][off] = half2 (x[off+..], x[off+1+..]) for off 0..4
            __half2 xw[3][5];
#pragma unroll
            for (int dr = 0; dr < 3; ++dr) {
                int wi = c * XS_C + (r + dr) * XROW + (cg >> 1);   // even word idx
                uint2    h01 = *reinterpret_cast<const uint2*>(xsb + wi);
                unsigned h2  = xsb[wi + 2];
                unsigned s1  = __byte_perm(h01.x, h01.y, 0x5432);
                unsigned s3  = __byte_perm(h01.y, h2,    0x5432);
                xw[dr][0] = *reinterpret_cast<__half2*>(&h01.x);
                xw[dr][1] = *reinterpret_cast<__half2*>(&s1);
                xw[dr][2] = *reinterpret_cast<__half2*>(&h01.y);
                xw[dr][3] = *reinterpret_cast<__half2*>(&s3);
                xw[dr][4] = *reinterpret_cast<__half2*>(&h2);
            }
            const unsigned* wrow = wsb + c * WS_C + (cog * COT) * WPC;
#pragma unroll
            for (int u = 0; u < COT; ++u) {
                uint4 q0 = *reinterpret_cast<const uint4*>(wrow + u * WPC);
                uint4 q1 = *reinterpret_cast<const uint4*>(wrow + u * WPC + 4);
                unsigned t8 = wrow[u * WPC + 8];
                unsigned tw[9] = { q0.x, q0.y, q0.z, q0.w, q1.x, q1.y, q1.z, q1.w, t8 };
#pragma unroll
                for (int dr = 0; dr < 3; ++dr)
#pragma unroll
                    for (int dc = 0; dc < 3; ++dc) {
                        __half2 t = *reinterpret_cast<__half2*>(&tw[dr * 3 + dc]);
                        A[u][0] = __hmax2(A[u][0], __hadd2(xw[dr][dc],     t));
                        A[u][1] = __hmax2(A[u][1], __hadd2(xw[dr][dc + 2], t));
                    }
            }
        }
        buf ^= 1;
    }

    // ---- epilogue: fp16 -> fp32, float4 store ----
#pragma unroll
    for (int u = 0; u < COT; ++u) {
        const int co = co0 + cog * COT + u;
        float* op = out + (((size_t)b * COUT + co) * H + (h0 + r)) * W + w0 + cg;
        float2 lo = __half22float2(A[u][0]);
        float2 hi = __half22float2(A[u][1]);
        *reinterpret_cast<float4*>(op) = make_float4(lo.x, lo.y, hi.x, hi.y);
    }
}

extern "C" void kernel_launch(void* const* d_in, const int* in_sizes, int n_in,
                              void* d_out, int out_size)
{
    const float* x   = (const float*)d_in[0];
    const float* wgt = (const float*)d_in[1];
    float* out       = (float*)d_out;

    const int nx = B * CIN * XPC;                 // half2 words
    prep_x<<<(nx + 255) / 256, 256>>>(x);
    const int nw = CIN * COUT * WPC;
    prep_w<<<(nw + 255) / 256, 256>>>(wgt);

    dim3 grid(W / TW, H / TH, B * (COUT / COB));  // 1024 blocks
    maxconv2d_kernel<<<grid, 128>>>(out);
}